// round 13
// baseline (speedup 1.0000x reference)
#include <cuda_runtime.h>
#include <cuda_fp16.h>
#include <cstdint>
#include <cstddef>

// ---------------------------------------------------------------------------
// Shapes (fixed per reference)
// ---------------------------------------------------------------------------
#define Bb 4
#define Ss 4096
#define Dd 1024
#define Mm (Bb * Ss)   // 16384
#define Nn (2 * Dd)    // 2048
#define Kk (Dd)        // 1024

// GEMM tiling
#define TM 128
#define TN 128
#define TKC 64               // K elements per pipeline chunk (128 B rows)
#define NKC (Kk / TKC)       // 16 chunks
#define NSTAGE 3
#define NTHR 128             // 4 warps, 2x2 warp grid, warp tile 64x64

// Scan chunking: 32-step chunks (four per GEMM row-block)
#define NCH 4096             // channels = Bb*Dd
#define CLEN 32
#define NCHUNK (Ss / CLEN)   // 128

// ---------------------------------------------------------------------------
// Static device scratch (allocation-free rule)
// ---------------------------------------------------------------------------
__device__ __half2 g_AV[(size_t)Mm * Dd];     // 64 MiB  (a_t, v_t) packed fp16
__device__ __half  g_Xh[(size_t)Mm * Kk];     // 32 MiB  fp16 of x
__device__ __half  g_Wh[(size_t)Nn * Kk];     // 4 MiB   fp16 of W, rows interleaved
__device__ float   g_Achk[NCH * NCHUNK];      // [ch][chunk]
__device__ float   g_Hend[NCH * NCHUNK];      // [ch][chunk]
__device__ float   g_Hin [NCH * NCHUNK];      // [ch][chunk]

// ---------------------------------------------------------------------------
// PTX helpers (sm_103 baseline: cp.async, ldmatrix, mma.sync)
// ---------------------------------------------------------------------------
__device__ __forceinline__ uint32_t smem_u32(const void* p) {
    return (uint32_t)__cvta_generic_to_shared(p);
}

#define CP_ASYNC16(s, g) \
    asm volatile("cp.async.cg.shared.global [%0], [%1], 16;\n" :: "r"(s), "l"(g))
#define CP_COMMIT() asm volatile("cp.async.commit_group;\n" ::: "memory")
#define CP_WAIT(n)  asm volatile("cp.async.wait_group %0;\n" :: "n"(n) : "memory")

#define LDSM_X4(r0, r1, r2, r3, a)                                              \
    asm volatile("ldmatrix.sync.aligned.m8n8.x4.shared.b16 {%0,%1,%2,%3}, [%4];" \
                 : "=r"(r0), "=r"(r1), "=r"(r2), "=r"(r3) : "r"(a))

#define MMA16816F16(d, a, b)                                                    \
    asm volatile("mma.sync.aligned.m16n8k16.row.col.f32.f16.f16.f32 "           \
                 "{%0,%1,%2,%3}, {%4,%5,%6,%7}, {%8,%9}, {%0,%1,%2,%3};"        \
                 : "+f"((d)[0]), "+f"((d)[1]), "+f"((d)[2]), "+f"((d)[3])       \
                 : "r"((a)[0]), "r"((a)[1]), "r"((a)[2]), "r"((a)[3]),          \
                   "r"((b)[0]), "r"((b)[1]))

// ---------------------------------------------------------------------------
// Gate math: a = sigmoid(-gt), v = sigmoid(gt) * g(hid)
// ---------------------------------------------------------------------------
__device__ __forceinline__ void gate_math(float gt, float hid, float& a, float& v) {
    float q = __expf(-fabsf(gt));
    float r = __fdividef(1.0f, 1.0f + q);
    float z, aa;
    if (gt >= 0.0f) { z = r;     aa = q * r; }
    else            { z = q * r; aa = r;     }
    float g;
    if (hid >= 0.0f) g = hid + 0.5f;
    else {
        float q2 = __expf(hid);
        g = __fdividef(q2, 1.0f + q2);
    }
    a = aa;
    v = z * g;
}

// ---------------------------------------------------------------------------
// Kernel 0: fp32 x -> fp16; fp32 W -> fp16 with rows interleaved:
//   Wr[2d] = W[d] (hidden row), Wr[2d+1] = W[Dd+d] (gate row)
// ---------------------------------------------------------------------------
__global__ __launch_bounds__(256) void split_kernel(const float* __restrict__ x,
                                                    const float* __restrict__ w) {
    const size_t NX4 = (size_t)Mm * Kk / 4;
    const size_t NW4 = (size_t)Nn * Kk / 4;
    size_t i = (size_t)blockIdx.x * 256 + threadIdx.x;
    if (i < NX4) {
        float4 v = ((const float4*)x)[i];
        unsigned short hs[4] = {
            __half_as_ushort(__float2half_rn(v.x)),
            __half_as_ushort(__float2half_rn(v.y)),
            __half_as_ushort(__float2half_rn(v.z)),
            __half_as_ushort(__float2half_rn(v.w))};
        *(uint2*)(g_Xh + 4 * i) = make_uint2((uint32_t)hs[0] | ((uint32_t)hs[1] << 16),
                                             (uint32_t)hs[2] | ((uint32_t)hs[3] << 16));
    } else if (i < NX4 + NW4) {
        size_t j = i - NX4;
        int e  = (int)(j >> 8);
        int c4 = (int)(j & 255);
        int er = (e < Dd) ? (2 * e) : (2 * (e - Dd) + 1);
        float4 v = ((const float4*)w)[j];
        unsigned short hs[4] = {
            __half_as_ushort(__float2half_rn(v.x)),
            __half_as_ushort(__float2half_rn(v.y)),
            __half_as_ushort(__float2half_rn(v.z)),
            __half_as_ushort(__float2half_rn(v.w))};
        *(uint2*)(g_Wh + (size_t)er * Kk + c4 * 4) =
            make_uint2((uint32_t)hs[0] | ((uint32_t)hs[1] << 16),
                       (uint32_t)hs[2] | ((uint32_t)hs[3] << 16));
    }
}

// ---------------------------------------------------------------------------
// Kernel 1: fp16 GEMM (CTA 128x128, 4 warps, warp tile 64x64, occ 2,
// TKC=64, 3 stages) + fused gate epilogue + per-32-row chunk summaries.
// ---------------------------------------------------------------------------
#define SOFF_XH 0
#define SOFF_WH 16384
#define STAGE_BYTES 32768
#define SMEM_DYN (NSTAGE * STAGE_BYTES)   // 96 KiB; epilogue reuses it

// epilogue smem layout (overlaps stages after sync):
//   __half2 av[128][AV_STRIDE]
#define AV_STRIDE 65

// 128-byte-row swizzle: 16B chunk index xor'd with row&7
__device__ __forceinline__ uint32_t sw_off(int row, int chunk) {
    return (uint32_t)(row * 128 + ((chunk ^ (row & 7)) << 4));
}

__device__ __forceinline__ void load_stage(int kc, uint32_t sb, int bm, int bn, int tid) {
    const int k0 = kc * TKC;
#pragma unroll
    for (int j = 0; j < 16; j++) {
        int q = tid + j * NTHR;         // 0..2047
        int row = q >> 3;               // 0..255 (X:0-127, W:128-255)
        int ch = q & 7;                 // 16B chunk within 128B row
        if (row < 128) {
            uint32_t so = sw_off(row, ch);
            size_t ga = (size_t)(bm + row) * Kk + k0 + ch * 8;
            CP_ASYNC16(sb + SOFF_XH + so, g_Xh + ga);
        } else {
            int wr = row - 128;
            uint32_t so = sw_off(wr, ch);
            size_t gw = (size_t)(bn + wr) * Kk + k0 + ch * 8;
            CP_ASYNC16(sb + SOFF_WH + so, g_Wh + gw);
        }
    }
    CP_COMMIT();
}

__global__ __launch_bounds__(NTHR, 2) void gemm_kernel() {
    extern __shared__ char smraw[];
    const uint32_t sm0 = smem_u32(smraw);

    const int tid = threadIdx.x;
    const int wid = tid >> 5;
    const int lane = tid & 31;
    const int bm = blockIdx.y * TM;
    const int bn = blockIdx.x * TN;

    const int warp_m = (wid & 1) * 64;   // 0 / 64
    const int warp_n = (wid >> 1) * 64;  // 0 / 64

    const int lrow = lane & 15;
    const int lsel = lane >> 4;

    float acc[4][8][4];
#pragma unroll
    for (int i = 0; i < 4; i++)
#pragma unroll
        for (int j = 0; j < 8; j++)
#pragma unroll
            for (int r = 0; r < 4; r++) acc[i][j][r] = 0.0f;

    // prefetch distance 2 (one buffer always free)
    load_stage(0, sm0, bm, bn, tid);
    load_stage(1, sm0 + STAGE_BYTES, bm, bn, tid);

    for (int kc = 0; kc < NKC; kc++) {
        CP_WAIT(1);
        __syncthreads();
        if (kc + 2 < NKC)
            load_stage(kc + 2, sm0 + (uint32_t)((kc + 2) % NSTAGE) * STAGE_BYTES,
                       bm, bn, tid);

        const uint32_t sb = sm0 + (uint32_t)(kc % NSTAGE) * STAGE_BYTES;
#pragma unroll
        for (int ks = 0; ks < 4; ks++) {
            uint32_t aX[4][4], bW[8][2];
            const int chunk = 2 * ks + lsel;
#pragma unroll
            for (int mt = 0; mt < 4; mt++) {
                uint32_t so = sw_off(warp_m + mt * 16 + lrow, chunk);
                LDSM_X4(aX[mt][0], aX[mt][1], aX[mt][2], aX[mt][3], sb + SOFF_XH + so);
            }
#pragma unroll
            for (int ng = 0; ng < 4; ng++) {
                uint32_t so = sw_off(warp_n + ng * 16 + lrow, chunk);
                uint32_t r0, r1, r2, r3;
                LDSM_X4(r0, r1, r2, r3, sb + SOFF_WH + so);
                bW[ng * 2 + 0][0] = r0; bW[ng * 2 + 0][1] = r2;
                bW[ng * 2 + 1][0] = r1; bW[ng * 2 + 1][1] = r3;
            }
#pragma unroll
            for (int mt = 0; mt < 4; mt++)
#pragma unroll
                for (int nt = 0; nt < 8; nt++)
                    MMA16816F16(acc[mt][nt], aX[mt], bW[nt]);
        }
    }

    // ---------------- fused epilogue ----------------
    __syncthreads();                 // done with stage buffers; reuse smem
    __half2* av = (__half2*)smraw;   // [128][AV_STRIDE]

    const int erow = lane >> 2;
    const int chq  = lane & 3;
    const int wch  = warp_n >> 1;    // warp channel offset (0 / 32)
#pragma unroll
    for (int mt = 0; mt < 4; mt++)
#pragma unroll
        for (int nt = 0; nt < 8; nt++) {
            int rloc = warp_m + mt * 16 + erow;
            int cloc = wch + nt * 4 + chq;
            float a0, v0, a1, v1;
            gate_math(acc[mt][nt][1], acc[mt][nt][0], a0, v0);
            gate_math(acc[mt][nt][3], acc[mt][nt][2], a1, v1);
            av[rloc * AV_STRIDE + cloc]       = __floats2half2_rn(a0, v0);
            av[(rloc + 8) * AV_STRIDE + cloc] = __floats2half2_rn(a1, v1);
        }
    __syncthreads();

    // coalesced global write of the (a,v) tile: 128 rows x 64 ch x 4B
    {
        const int chbase = bn >> 1;
#pragma unroll
        for (int i = tid; i < 128 * 64; i += NTHR) {
            int row = i >> 6, ch = i & 63;
            g_AV[(size_t)(bm + row) * Dd + chbase + ch] = av[row * AV_STRIDE + ch];
        }
    }

    // per-32-row chunk summaries (4 chunks per CTA), stored transposed;
    // 128 threads handle 4 segs x 64 channels = 2 tasks each
    {
        const int chl = tid & 63;          // 0..63
        const int s0  = tid >> 6;          // 0..1
#pragma unroll
        for (int s2 = 0; s2 < 2; s2++) {
            const int seg = s0 + 2 * s2;   // 0..3
            float A = 1.0f, H = 0.0f;
#pragma unroll 8
            for (int i = 0; i < 32; i++) {
                float2 p = __half22float2(av[(seg * 32 + i) * AV_STRIDE + chl]);
                H = fmaf(p.x, H, p.y);
                A *= p.x;
            }
            const int b = bm >> 12;
            const int c = ((bm & (Ss - 1)) >> 5) + seg;      // chunk 0..127
            const int chg = b * Dd + (bn >> 1) + chl;        // global channel
            g_Achk[chg * NCHUNK + c] = A;
            g_Hend[chg * NCHUNK + c] = H;
        }
    }
}

// ---------------------------------------------------------------------------
// Pass 2: warp-parallel scan over 128 chunk summaries (1 warp/channel,
// 4 chunks/lane), coalesced [ch][chunk] layout.
// ---------------------------------------------------------------------------
__global__ __launch_bounds__(256) void scan_pass2() {
    int warp = (blockIdx.x * 256 + threadIdx.x) >> 5;   // channel 0..4095
    int lane = threadIdx.x & 31;
    const int c0 = 4 * lane;

    float4 Av = *(const float4*)(g_Achk + warp * NCHUNK + c0);
    float4 Hv = *(const float4*)(g_Hend + warp * NCHUNK + c0);

    // compose the 4 local chunks: running prefix within the lane
    float A01 = Av.x * Av.y;
    float H01 = fmaf(Av.y, Hv.x, Hv.y);
    float A012 = A01 * Av.z;
    float H012 = fmaf(Av.z, H01, Hv.z);
    float Ai = A012 * Av.w;
    float Hi = fmaf(Av.w, H012, Hv.w);

#pragma unroll
    for (int d = 1; d < 32; d <<= 1) {
        float Au = __shfl_up_sync(0xFFFFFFFFu, Ai, d);
        float Hu = __shfl_up_sync(0xFFFFFFFFu, Hi, d);
        if (lane >= d) {
            Hi = fmaf(Ai, Hu, Hi);
            Ai = Au * Ai;
        }
    }
    float Hex = __shfl_up_sync(0xFFFFFFFFu, Hi, 1);
    if (lane == 0) Hex = 0.0f;

    // carry-ins for the 4 local chunks
    float4 Hin;
    Hin.x = Hex;
    Hin.y = fmaf(Av.x, Hex, Hv.x);
    Hin.z = fmaf(A01,  Hex, H01);
    Hin.w = fmaf(A012, Hex, H012);
    *(float4*)(g_Hin + warp * NCHUNK + c0) = Hin;
}

// ---------------------------------------------------------------------------
// Pass 3: recompute with carry-in over 32-step chunks (524288 threads).
// ---------------------------------------------------------------------------
__global__ __launch_bounds__(256) void scan_pass3(float* __restrict__ out) {
    int idx = blockIdx.x * 256 + threadIdx.x;           // 524288
    int ch = idx & (NCH - 1);
    int c  = idx >> 12;                                 // 0..127
    int b = ch >> 10, d = ch & (Dd - 1);
    size_t base = ((size_t)b * Ss + (size_t)c * CLEN) * Dd + d;
    float* orow = out + base;
    float h = g_Hin[ch * NCHUNK + c];
#pragma unroll 8
    for (int t = 0; t < CLEN; t++) {
        float2 p = __half22float2(g_AV[base]);
        base += Dd;
        h = fmaf(p.x, h, p.y);
        *orow = h;
        orow += Dd;
    }
}

// ---------------------------------------------------------------------------
extern "C" void kernel_launch(void* const* d_in, const int* in_sizes, int n_in,
                              void* d_out, int out_size)
{
    const float* x = (const float*)d_in[0];
    const float* W = (const float*)d_in[1];
    float* out = (float*)d_out;

    cudaFuncSetAttribute(gemm_kernel, cudaFuncAttributeMaxDynamicSharedMemorySize, SMEM_DYN);

    const int nsplit = (int)(((size_t)Mm * Kk / 4 + (size_t)Nn * Kk / 4) / 256);
    split_kernel<<<nsplit, 256>>>(x, W);

    gemm_kernel<<<dim3(Nn / TN, Mm / TM), NTHR, SMEM_DYN>>>();

    scan_pass2<<<(NCH * 32) / 256, 256>>>();
    scan_pass3<<<(NCH * NCHUNK) / 256, 256>>>(out);
}

// round 14
// speedup vs baseline: 1.0286x; 1.0286x over previous
#include <cuda_runtime.h>
#include <cuda_fp16.h>
#include <cstdint>
#include <cstddef>

// ---------------------------------------------------------------------------
// Shapes (fixed per reference)
// ---------------------------------------------------------------------------
#define Bb 4
#define Ss 4096
#define Dd 1024
#define Mm (Bb * Ss)   // 16384
#define Nn (2 * Dd)    // 2048
#define Kk (Dd)        // 1024

// GEMM tiling (R12 proven config)
#define TM 128
#define TN 128
#define TKC 64               // K elements per pipeline chunk (128 B rows)
#define NKC (Kk / TKC)       // 16 chunks
#define NSTAGE 3

// Scan chunking: 32-step chunks (four per GEMM row-block)
#define NCH 4096             // channels = Bb*Dd
#define CLEN 32
#define NCHUNK (Ss / CLEN)   // 128

// ---------------------------------------------------------------------------
// Static device scratch (allocation-free rule)
// ---------------------------------------------------------------------------
__device__ __half2 g_AV[(size_t)Mm * Dd];     // 64 MiB  (a_t, v_t) packed fp16
__device__ __half  g_Xh[(size_t)Mm * Kk];     // 32 MiB  fp16 of x
__device__ __half  g_Wh[(size_t)Nn * Kk];     // 4 MiB   fp16 of W, rows interleaved
__device__ float   g_Achk[NCH * NCHUNK];      // [ch][chunk]
__device__ float   g_Hend[NCH * NCHUNK];      // [ch][chunk]
__device__ float   g_Hin [NCH * NCHUNK];      // [ch][chunk]

// ---------------------------------------------------------------------------
// PTX helpers (sm_103 baseline: cp.async, ldmatrix, mma.sync)
// ---------------------------------------------------------------------------
__device__ __forceinline__ uint32_t smem_u32(const void* p) {
    return (uint32_t)__cvta_generic_to_shared(p);
}

#define CP_ASYNC16(s, g) \
    asm volatile("cp.async.cg.shared.global [%0], [%1], 16;\n" :: "r"(s), "l"(g))
#define CP_COMMIT() asm volatile("cp.async.commit_group;\n" ::: "memory")
#define CP_WAIT(n)  asm volatile("cp.async.wait_group %0;\n" :: "n"(n) : "memory")

#define LDSM_X4(r0, r1, r2, r3, a)                                              \
    asm volatile("ldmatrix.sync.aligned.m8n8.x4.shared.b16 {%0,%1,%2,%3}, [%4];" \
                 : "=r"(r0), "=r"(r1), "=r"(r2), "=r"(r3) : "r"(a))

#define MMA16816F16(d, a, b)                                                    \
    asm volatile("mma.sync.aligned.m16n8k16.row.col.f32.f16.f16.f32 "           \
                 "{%0,%1,%2,%3}, {%4,%5,%6,%7}, {%8,%9}, {%0,%1,%2,%3};"        \
                 : "+f"((d)[0]), "+f"((d)[1]), "+f"((d)[2]), "+f"((d)[3])       \
                 : "r"((a)[0]), "r"((a)[1]), "r"((a)[2]), "r"((a)[3]),          \
                   "r"((b)[0]), "r"((b)[1]))

// ---------------------------------------------------------------------------
// Gate math: a = sigmoid(-gt), v = sigmoid(gt) * g(hid)
// ---------------------------------------------------------------------------
__device__ __forceinline__ void gate_math(float gt, float hid, float& a, float& v) {
    float q = __expf(-fabsf(gt));
    float r = __fdividef(1.0f, 1.0f + q);
    float z, aa;
    if (gt >= 0.0f) { z = r;     aa = q * r; }
    else            { z = q * r; aa = r;     }
    float g;
    if (hid >= 0.0f) g = hid + 0.5f;
    else {
        float q2 = __expf(hid);
        g = __fdividef(q2, 1.0f + q2);
    }
    a = aa;
    v = z * g;
}

// ---------------------------------------------------------------------------
// Kernel 0: fp32 x -> fp16; fp32 W -> fp16 with rows interleaved:
//   Wr[2d] = W[d] (hidden row), Wr[2d+1] = W[Dd+d] (gate row)
// ---------------------------------------------------------------------------
__global__ __launch_bounds__(256) void split_kernel(const float* __restrict__ x,
                                                    const float* __restrict__ w) {
    const size_t NX4 = (size_t)Mm * Kk / 4;
    const size_t NW4 = (size_t)Nn * Kk / 4;
    size_t i = (size_t)blockIdx.x * 256 + threadIdx.x;
    if (i < NX4) {
        float4 v = ((const float4*)x)[i];
        unsigned short hs[4] = {
            __half_as_ushort(__float2half_rn(v.x)),
            __half_as_ushort(__float2half_rn(v.y)),
            __half_as_ushort(__float2half_rn(v.z)),
            __half_as_ushort(__float2half_rn(v.w))};
        *(uint2*)(g_Xh + 4 * i) = make_uint2((uint32_t)hs[0] | ((uint32_t)hs[1] << 16),
                                             (uint32_t)hs[2] | ((uint32_t)hs[3] << 16));
    } else if (i < NX4 + NW4) {
        size_t j = i - NX4;
        int e  = (int)(j >> 8);
        int c4 = (int)(j & 255);
        int er = (e < Dd) ? (2 * e) : (2 * (e - Dd) + 1);
        float4 v = ((const float4*)w)[j];
        unsigned short hs[4] = {
            __half_as_ushort(__float2half_rn(v.x)),
            __half_as_ushort(__float2half_rn(v.y)),
            __half_as_ushort(__float2half_rn(v.z)),
            __half_as_ushort(__float2half_rn(v.w))};
        *(uint2*)(g_Wh + (size_t)er * Kk + c4 * 4) =
            make_uint2((uint32_t)hs[0] | ((uint32_t)hs[1] << 16),
                       (uint32_t)hs[2] | ((uint32_t)hs[3] << 16));
    }
}

// ---------------------------------------------------------------------------
// Kernel 1: fp16 GEMM (CTA 128x128, 8 warps, warp tile 64x32, occ 2,
// TKC=64, 3 stages, compile-time stage rotation) + fused gate epilogue
// + per-32-row chunk summaries.
// ---------------------------------------------------------------------------
#define SOFF_XH 0
#define SOFF_WH 16384
#define STAGE_BYTES 32768
#define SMEM_DYN (NSTAGE * STAGE_BYTES)   // 96 KiB; epilogue reuses it

// epilogue smem layout (overlaps stages after sync):
//   __half2 av[128][AV_STRIDE]
#define AV_STRIDE 65

// 128-byte-row swizzle: 16B chunk index xor'd with row&7
__device__ __forceinline__ uint32_t sw_off(int row, int chunk) {
    return (uint32_t)(row * 128 + ((chunk ^ (row & 7)) << 4));
}

__device__ __forceinline__ void load_stage(int kc, uint32_t sb, int bm, int bn, int tid) {
    const int k0 = kc * TKC;
#pragma unroll
    for (int j = 0; j < 4; j++) {
        int q = tid + j * 256;          // 0..1023
        int row = q >> 3;               // 0..127
        int ch = q & 7;                 // 16B chunk within 128B row
        uint32_t so = sw_off(row, ch);
        size_t ga = (size_t)(bm + row) * Kk + k0 + ch * 8;
        size_t gw = (size_t)(bn + row) * Kk + k0 + ch * 8;
        CP_ASYNC16(sb + SOFF_XH + so, g_Xh + ga);
        CP_ASYNC16(sb + SOFF_WH + so, g_Wh + gw);
    }
    CP_COMMIT();
}

// one kc iteration body; stage offsets are compile-time constants
template <int SCUR>
__device__ __forceinline__ void gemm_step(int kc, uint32_t sm0, int bm, int bn,
                                          int tid, int warp_m, int warp_n,
                                          int lrow, int lsel,
                                          float acc[4][4][4]) {
    CP_WAIT(1);
    __syncthreads();
    if (kc + 2 < NKC)
        load_stage(kc + 2, sm0 + ((SCUR + 2) % NSTAGE) * STAGE_BYTES, bm, bn, tid);

    const uint32_t sb = sm0 + SCUR * STAGE_BYTES;
#pragma unroll
    for (int ks = 0; ks < 4; ks++) {
        uint32_t aX[4][4], bW[4][2];
        const int chunk = 2 * ks + lsel;
#pragma unroll
        for (int mt = 0; mt < 4; mt++) {
            uint32_t so = sw_off(warp_m + mt * 16 + lrow, chunk);
            LDSM_X4(aX[mt][0], aX[mt][1], aX[mt][2], aX[mt][3], sb + SOFF_XH + so);
        }
#pragma unroll
        for (int ng = 0; ng < 2; ng++) {
            uint32_t so = sw_off(warp_n + ng * 16 + lrow, chunk);
            uint32_t r0, r1, r2, r3;
            LDSM_X4(r0, r1, r2, r3, sb + SOFF_WH + so);
            bW[ng * 2 + 0][0] = r0; bW[ng * 2 + 0][1] = r2;
            bW[ng * 2 + 1][0] = r1; bW[ng * 2 + 1][1] = r3;
        }
#pragma unroll
        for (int mt = 0; mt < 4; mt++)
#pragma unroll
            for (int nt = 0; nt < 4; nt++)
                MMA16816F16(acc[mt][nt], aX[mt], bW[nt]);
    }
}

__global__ __launch_bounds__(256, 2) void gemm_kernel() {
    extern __shared__ char smraw[];
    const uint32_t sm0 = smem_u32(smraw);

    const int tid = threadIdx.x;
    const int wid = tid >> 5;
    const int lane = tid & 31;
    const int bm = blockIdx.y * TM;
    const int bn = blockIdx.x * TN;

    const int warp_m = (wid & 1) * 64;
    const int warp_n = (wid >> 1) * 32;

    const int lrow = lane & 15;
    const int lsel = lane >> 4;

    float acc[4][4][4];
#pragma unroll
    for (int i = 0; i < 4; i++)
#pragma unroll
        for (int j = 0; j < 4; j++)
#pragma unroll
            for (int r = 0; r < 4; r++) acc[i][j][r] = 0.0f;

    // prefetch distance 2 (one buffer always free)
    load_stage(0, sm0, bm, bn, tid);
    load_stage(1, sm0 + STAGE_BYTES, bm, bn, tid);

    // NKC = 16 = 5*3 + 1: unrolled-by-3 loop + one tail step
#pragma unroll 1
    for (int kc = 0; kc < 15; kc += 3) {
        gemm_step<0>(kc + 0, sm0, bm, bn, tid, warp_m, warp_n, lrow, lsel, acc);
        gemm_step<1>(kc + 1, sm0, bm, bn, tid, warp_m, warp_n, lrow, lsel, acc);
        gemm_step<2>(kc + 2, sm0, bm, bn, tid, warp_m, warp_n, lrow, lsel, acc);
    }
    gemm_step<0>(15, sm0, bm, bn, tid, warp_m, warp_n, lrow, lsel, acc);

    // ---------------- fused epilogue ----------------
    __syncthreads();                 // done with stage buffers; reuse smem
    __half2* av = (__half2*)smraw;   // [128][AV_STRIDE]

    const int erow = lane >> 2;
    const int chq  = lane & 3;
    const int wch  = warp_n >> 1;    // warp channel offset (0,16,32,48)
#pragma unroll
    for (int mt = 0; mt < 4; mt++)
#pragma unroll
        for (int nt = 0; nt < 4; nt++) {
            int rloc = warp_m + mt * 16 + erow;
            int cloc = wch + nt * 4 + chq;
            float a0, v0, a1, v1;
            gate_math(acc[mt][nt][1], acc[mt][nt][0], a0, v0);
            gate_math(acc[mt][nt][3], acc[mt][nt][2], a1, v1);
            av[rloc * AV_STRIDE + cloc]       = __floats2half2_rn(a0, v0);
            av[(rloc + 8) * AV_STRIDE + cloc] = __floats2half2_rn(a1, v1);
        }
    __syncthreads();

    // coalesced global write of the (a,v) tile: 128 rows x 64 ch x 4B
    {
        const int chbase = bn >> 1;
#pragma unroll
        for (int i = tid; i < 128 * 64; i += 256) {
            int row = i >> 6, ch = i & 63;
            g_AV[(size_t)(bm + row) * Dd + chbase + ch] = av[row * AV_STRIDE + ch];
        }
    }

    // per-32-row chunk summaries (4 chunks per CTA), stored transposed
    {
        const int seg = tid >> 6;          // 0..3
        const int chl = tid & 63;          // 0..63
        float A = 1.0f, H = 0.0f;
#pragma unroll 8
        for (int i = 0; i < 32; i++) {
            float2 p = __half22float2(av[(seg * 32 + i) * AV_STRIDE + chl]);
            H = fmaf(p.x, H, p.y);
            A *= p.x;
        }
        const int b = bm >> 12;
        const int c = ((bm & (Ss - 1)) >> 5) + seg;      // chunk index 0..127
        const int chg = b * Dd + (bn >> 1) + chl;        // global channel
        g_Achk[chg * NCHUNK + c] = A;
        g_Hend[chg * NCHUNK + c] = H;
    }
}

// ---------------------------------------------------------------------------
// Pass 2: warp-parallel scan over 128 chunk summaries (1 warp/channel,
// 4 chunks/lane), coalesced [ch][chunk] layout.
// ---------------------------------------------------------------------------
__global__ __launch_bounds__(256) void scan_pass2() {
    int warp = (blockIdx.x * 256 + threadIdx.x) >> 5;   // channel 0..4095
    int lane = threadIdx.x & 31;
    const int c0 = 4 * lane;

    float4 Av = *(const float4*)(g_Achk + warp * NCHUNK + c0);
    float4 Hv = *(const float4*)(g_Hend + warp * NCHUNK + c0);

    // compose the 4 local chunks: running prefix within the lane
    float A01 = Av.x * Av.y;
    float H01 = fmaf(Av.y, Hv.x, Hv.y);
    float A012 = A01 * Av.z;
    float H012 = fmaf(Av.z, H01, Hv.z);
    float Ai = A012 * Av.w;
    float Hi = fmaf(Av.w, H012, Hv.w);

#pragma unroll
    for (int d = 1; d < 32; d <<= 1) {
        float Au = __shfl_up_sync(0xFFFFFFFFu, Ai, d);
        float Hu = __shfl_up_sync(0xFFFFFFFFu, Hi, d);
        if (lane >= d) {
            Hi = fmaf(Ai, Hu, Hi);
            Ai = Au * Ai;
        }
    }
    float Hex = __shfl_up_sync(0xFFFFFFFFu, Hi, 1);
    if (lane == 0) Hex = 0.0f;

    // carry-ins for the 4 local chunks
    float4 Hin;
    Hin.x = Hex;
    Hin.y = fmaf(Av.x, Hex, Hv.x);
    Hin.z = fmaf(A01,  Hex, H01);
    Hin.w = fmaf(A012, Hex, H012);
    *(float4*)(g_Hin + warp * NCHUNK + c0) = Hin;
}

// ---------------------------------------------------------------------------
// Pass 3: recompute with carry-in over 32-step chunks, 2 channels/thread
// (uint2 loads, float2 stores; 262144 threads).
// ---------------------------------------------------------------------------
__global__ __launch_bounds__(256) void scan_pass3(float* __restrict__ out) {
    int idx = blockIdx.x * 256 + threadIdx.x;           // 262144
    int chp = idx & (NCH / 2 - 1);                      // channel pair 0..2047
    int c   = idx >> 11;                                // chunk 0..127
    int ch0 = 2 * chp;
    int b = ch0 >> 10, d0 = ch0 & (Dd - 1);

    size_t row0 = (size_t)b * Ss + (size_t)c * CLEN;
    const uint2* avp = (const uint2*)(g_AV + row0 * Dd + d0);
    float* op = out + row0 * Dd + d0;

    float h0 = g_Hin[ch0 * NCHUNK + c];
    float h1 = g_Hin[(ch0 + 1) * NCHUNK + c];
#pragma unroll 8
    for (int t = 0; t < CLEN; t++) {
        uint2 u = *avp;
        avp += Dd / 2;
        float2 p0 = __half22float2(*(__half2*)&u.x);
        float2 p1 = __half22float2(*(__half2*)&u.y);
        h0 = fmaf(p0.x, h0, p0.y);
        h1 = fmaf(p1.x, h1, p1.y);
        *(float2*)op = make_float2(h0, h1);
        op += Dd;
    }
}

// ---------------------------------------------------------------------------
extern "C" void kernel_launch(void* const* d_in, const int* in_sizes, int n_in,
                              void* d_out, int out_size)
{
    const float* x = (const float*)d_in[0];
    const float* W = (const float*)d_in[1];
    float* out = (float*)d_out;

    cudaFuncSetAttribute(gemm_kernel, cudaFuncAttributeMaxDynamicSharedMemorySize, SMEM_DYN);

    const int nsplit = (int)(((size_t)Mm * Kk / 4 + (size_t)Nn * Kk / 4) / 256);
    split_kernel<<<nsplit, 256>>>(x, W);

    gemm_kernel<<<dim3(Nn / TN, Mm / TM), 256, SMEM_DYN>>>();

    scan_pass2<<<(NCH * 32) / 256, 256>>>();
    scan_pass3<<<(NCH / 2 * NCHUNK) / 256, 256>>>(out);
}

// round 15
// speedup vs baseline: 1.0402x; 1.0113x over previous
#include <cuda_runtime.h>
#include <cuda_fp16.h>
#include <cstdint>
#include <cstddef>

// ---------------------------------------------------------------------------
// Shapes (fixed per reference)
// ---------------------------------------------------------------------------
#define Bb 4
#define Ss 4096
#define Dd 1024
#define Mm (Bb * Ss)   // 16384
#define Nn (2 * Dd)    // 2048
#define Kk (Dd)        // 1024

// GEMM tiling (R12 proven config)
#define TM 128
#define TN 128
#define TKC 64               // K elements per pipeline chunk (128 B rows)
#define NKC (Kk / TKC)       // 16 chunks
#define NSTAGE 3

// Scan chunking: 32-step chunks (four per GEMM row-block)
#define NCH 4096             // channels = Bb*Dd
#define CLEN 32
#define NCHUNK (Ss / CLEN)   // 128

// ---------------------------------------------------------------------------
// Static device scratch (allocation-free rule)
// ---------------------------------------------------------------------------
__device__ __half2 g_AV[(size_t)Mm * Dd];     // 64 MiB  (a_t, v_t) packed fp16
__device__ __half  g_Xh[(size_t)Mm * Kk];     // 32 MiB  fp16 of x
__device__ __half  g_Wh[(size_t)Nn * Kk];     // 4 MiB   fp16 of W, rows interleaved
__device__ float   g_Achk[NCH * NCHUNK];      // [ch][chunk]
__device__ float   g_Hend[NCH * NCHUNK];      // [ch][chunk]
__device__ float   g_Hin [NCH * NCHUNK];      // [ch][chunk]

// ---------------------------------------------------------------------------
// PTX helpers (sm_103 baseline: cp.async, ldmatrix, mma.sync)
// ---------------------------------------------------------------------------
__device__ __forceinline__ uint32_t smem_u32(const void* p) {
    return (uint32_t)__cvta_generic_to_shared(p);
}

#define CP_ASYNC16(s, g) \
    asm volatile("cp.async.cg.shared.global [%0], [%1], 16;\n" :: "r"(s), "l"(g))
#define CP_COMMIT() asm volatile("cp.async.commit_group;\n" ::: "memory")
#define CP_WAIT(n)  asm volatile("cp.async.wait_group %0;\n" :: "n"(n) : "memory")

#define LDSM_X4(r0, r1, r2, r3, a)                                              \
    asm volatile("ldmatrix.sync.aligned.m8n8.x4.shared.b16 {%0,%1,%2,%3}, [%4];" \
                 : "=r"(r0), "=r"(r1), "=r"(r2), "=r"(r3) : "r"(a))

#define MMA16816F16(d, a, b)                                                    \
    asm volatile("mma.sync.aligned.m16n8k16.row.col.f32.f16.f16.f32 "           \
                 "{%0,%1,%2,%3}, {%4,%5,%6,%7}, {%8,%9}, {%0,%1,%2,%3};"        \
                 : "+f"((d)[0]), "+f"((d)[1]), "+f"((d)[2]), "+f"((d)[3])       \
                 : "r"((a)[0]), "r"((a)[1]), "r"((a)[2]), "r"((a)[3]),          \
                   "r"((b)[0]), "r"((b)[1]))

// ---------------------------------------------------------------------------
// Gate math: a = sigmoid(-gt), v = sigmoid(gt) * g(hid)
// ---------------------------------------------------------------------------
__device__ __forceinline__ void gate_math(float gt, float hid, float& a, float& v) {
    float q = __expf(-fabsf(gt));
    float r = __fdividef(1.0f, 1.0f + q);
    float z, aa;
    if (gt >= 0.0f) { z = r;     aa = q * r; }
    else            { z = q * r; aa = r;     }
    float g;
    if (hid >= 0.0f) g = hid + 0.5f;
    else {
        float q2 = __expf(hid);
        g = __fdividef(q2, 1.0f + q2);
    }
    a = aa;
    v = z * g;
}

// ---------------------------------------------------------------------------
// Kernel 0: fp32 x -> fp16; fp32 W -> fp16 with rows interleaved:
//   Wr[2d] = W[d] (hidden row), Wr[2d+1] = W[Dd+d] (gate row)
// ---------------------------------------------------------------------------
__global__ __launch_bounds__(256) void split_kernel(const float* __restrict__ x,
                                                    const float* __restrict__ w) {
    const size_t NX4 = (size_t)Mm * Kk / 4;
    const size_t NW4 = (size_t)Nn * Kk / 4;
    size_t i = (size_t)blockIdx.x * 256 + threadIdx.x;
    if (i < NX4) {
        float4 v = ((const float4*)x)[i];
        unsigned short hs[4] = {
            __half_as_ushort(__float2half_rn(v.x)),
            __half_as_ushort(__float2half_rn(v.y)),
            __half_as_ushort(__float2half_rn(v.z)),
            __half_as_ushort(__float2half_rn(v.w))};
        *(uint2*)(g_Xh + 4 * i) = make_uint2((uint32_t)hs[0] | ((uint32_t)hs[1] << 16),
                                             (uint32_t)hs[2] | ((uint32_t)hs[3] << 16));
    } else if (i < NX4 + NW4) {
        size_t j = i - NX4;
        int e  = (int)(j >> 8);
        int c4 = (int)(j & 255);
        int er = (e < Dd) ? (2 * e) : (2 * (e - Dd) + 1);
        float4 v = ((const float4*)w)[j];
        unsigned short hs[4] = {
            __half_as_ushort(__float2half_rn(v.x)),
            __half_as_ushort(__float2half_rn(v.y)),
            __half_as_ushort(__float2half_rn(v.z)),
            __half_as_ushort(__float2half_rn(v.w))};
        *(uint2*)(g_Wh + (size_t)er * Kk + c4 * 4) =
            make_uint2((uint32_t)hs[0] | ((uint32_t)hs[1] << 16),
                       (uint32_t)hs[2] | ((uint32_t)hs[3] << 16));
    }
}

// ---------------------------------------------------------------------------
// Kernel 1: fp16 GEMM (CTA 128x128, 8 warps, warp tile 64x32, occ 2,
// TKC=64, 3 stages) + fused gate epilogue + per-32-row chunk summaries.
// ---------------------------------------------------------------------------
#define SOFF_XH 0
#define SOFF_WH 16384
#define STAGE_BYTES 32768
#define SMEM_DYN (NSTAGE * STAGE_BYTES)   // 96 KiB; epilogue reuses it

// epilogue smem layout (overlaps stages after sync):
//   __half2 av[128][AV_STRIDE]  (stride 66 -> 8B-aligned rows)
#define AV_STRIDE 66

// 128-byte-row swizzle: 16B chunk index xor'd with row&7
__device__ __forceinline__ uint32_t sw_off(int row, int chunk) {
    return (uint32_t)(row * 128 + ((chunk ^ (row & 7)) << 4));
}

__device__ __forceinline__ void load_stage(int kc, uint32_t sb, int bm, int bn, int tid) {
    const int k0 = kc * TKC;
#pragma unroll
    for (int j = 0; j < 4; j++) {
        int q = tid + j * 256;          // 0..1023
        int row = q >> 3;               // 0..127
        int ch = q & 7;                 // 16B chunk within 128B row
        uint32_t so = sw_off(row, ch);
        size_t ga = (size_t)(bm + row) * Kk + k0 + ch * 8;
        size_t gw = (size_t)(bn + row) * Kk + k0 + ch * 8;
        CP_ASYNC16(sb + SOFF_XH + so, g_Xh + ga);
        CP_ASYNC16(sb + SOFF_WH + so, g_Wh + gw);
    }
    CP_COMMIT();
}

__global__ __launch_bounds__(256, 2) void gemm_kernel() {
    extern __shared__ char smraw[];
    const uint32_t sm0 = smem_u32(smraw);

    const int tid = threadIdx.x;
    const int wid = tid >> 5;
    const int lane = tid & 31;
    const int bm = blockIdx.y * TM;
    const int bn = blockIdx.x * TN;

    const int warp_m = (wid & 1) * 64;
    const int warp_n = (wid >> 1) * 32;

    const int lrow = lane & 15;
    const int lsel = lane >> 4;

    float acc[4][4][4];
#pragma unroll
    for (int i = 0; i < 4; i++)
#pragma unroll
        for (int j = 0; j < 4; j++)
#pragma unroll
            for (int r = 0; r < 4; r++) acc[i][j][r] = 0.0f;

    // prefetch distance 2 (one buffer always free)
    load_stage(0, sm0, bm, bn, tid);
    load_stage(1, sm0 + STAGE_BYTES, bm, bn, tid);

    for (int kc = 0; kc < NKC; kc++) {
        CP_WAIT(1);
        __syncthreads();
        if (kc + 2 < NKC)
            load_stage(kc + 2, sm0 + (uint32_t)((kc + 2) % NSTAGE) * STAGE_BYTES,
                       bm, bn, tid);

        const uint32_t sb = sm0 + (uint32_t)(kc % NSTAGE) * STAGE_BYTES;
#pragma unroll
        for (int ks = 0; ks < 4; ks++) {
            uint32_t aX[4][4], bW[4][2];
            const int chunk = 2 * ks + lsel;
#pragma unroll
            for (int mt = 0; mt < 4; mt++) {
                uint32_t so = sw_off(warp_m + mt * 16 + lrow, chunk);
                LDSM_X4(aX[mt][0], aX[mt][1], aX[mt][2], aX[mt][3], sb + SOFF_XH + so);
            }
#pragma unroll
            for (int ng = 0; ng < 2; ng++) {
                uint32_t so = sw_off(warp_n + ng * 16 + lrow, chunk);
                uint32_t r0, r1, r2, r3;
                LDSM_X4(r0, r1, r2, r3, sb + SOFF_WH + so);
                bW[ng * 2 + 0][0] = r0; bW[ng * 2 + 0][1] = r2;
                bW[ng * 2 + 1][0] = r1; bW[ng * 2 + 1][1] = r3;
            }
#pragma unroll
            for (int mt = 0; mt < 4; mt++)
#pragma unroll
                for (int nt = 0; nt < 4; nt++)
                    MMA16816F16(acc[mt][nt], aX[mt], bW[nt]);
        }
    }

    // ---------------- fused epilogue ----------------
    __syncthreads();                 // done with stage buffers; reuse smem
    __half2* av = (__half2*)smraw;   // [128][AV_STRIDE]

    const int erow = lane >> 2;
    const int chq  = lane & 3;
    const int wch  = warp_n >> 1;    // warp channel offset (0,16,32,48)
#pragma unroll
    for (int mt = 0; mt < 4; mt++)
#pragma unroll
        for (int nt = 0; nt < 4; nt++) {
            int rloc = warp_m + mt * 16 + erow;
            int cloc = wch + nt * 4 + chq;
            float a0, v0, a1, v1;
            gate_math(acc[mt][nt][1], acc[mt][nt][0], a0, v0);
            gate_math(acc[mt][nt][3], acc[mt][nt][2], a1, v1);
            av[rloc * AV_STRIDE + cloc]       = __floats2half2_rn(a0, v0);
            av[(rloc + 8) * AV_STRIDE + cloc] = __floats2half2_rn(a1, v1);
        }
    __syncthreads();

    // coalesced global write of the (a,v) tile: 128 rows x 64 ch, uint2 (2 ch)
    {
        const int chbase = bn >> 1;
#pragma unroll
        for (int i = tid; i < 128 * 32; i += 256) {
            int row = i >> 5, chp = (i & 31) * 2;
            uint2 u = *(const uint2*)&av[row * AV_STRIDE + chp];
            *(uint2*)&g_AV[(size_t)(bm + row) * Dd + chbase + chp] = u;
        }
    }

    // per-32-row chunk summaries (4 chunks per CTA), stored transposed;
    // two independent 16-step chains per segment, composed at the end
    {
        const int seg = tid >> 6;          // 0..3
        const int chl = tid & 63;          // 0..63
        float A0 = 1.0f, H0 = 0.0f;        // rows seg*32 .. +15
        float A1 = 1.0f, H1 = 0.0f;        // rows seg*32+16 .. +31
#pragma unroll 4
        for (int i = 0; i < 16; i++) {
            float2 p0 = __half22float2(av[(seg * 32 + i) * AV_STRIDE + chl]);
            float2 p1 = __half22float2(av[(seg * 32 + 16 + i) * AV_STRIDE + chl]);
            H0 = fmaf(p0.x, H0, p0.y);
            A0 *= p0.x;
            H1 = fmaf(p1.x, H1, p1.y);
            A1 *= p1.x;
        }
        float A = A0 * A1;
        float H = fmaf(A1, H0, H1);
        const int b = bm >> 12;
        const int c = ((bm & (Ss - 1)) >> 5) + seg;      // chunk index 0..127
        const int chg = b * Dd + (bn >> 1) + chl;        // global channel
        g_Achk[chg * NCHUNK + c] = A;
        g_Hend[chg * NCHUNK + c] = H;
    }
}

// ---------------------------------------------------------------------------
// Pass 2: warp-parallel scan over 128 chunk summaries (1 warp/channel,
// 4 chunks/lane), coalesced [ch][chunk] layout.
// ---------------------------------------------------------------------------
__global__ __launch_bounds__(256) void scan_pass2() {
    int warp = (blockIdx.x * 256 + threadIdx.x) >> 5;   // channel 0..4095
    int lane = threadIdx.x & 31;
    const int c0 = 4 * lane;

    float4 Av = *(const float4*)(g_Achk + warp * NCHUNK + c0);
    float4 Hv = *(const float4*)(g_Hend + warp * NCHUNK + c0);

    // compose the 4 local chunks: running prefix within the lane
    float A01 = Av.x * Av.y;
    float H01 = fmaf(Av.y, Hv.x, Hv.y);
    float A012 = A01 * Av.z;
    float H012 = fmaf(Av.z, H01, Hv.z);
    float Ai = A012 * Av.w;
    float Hi = fmaf(Av.w, H012, Hv.w);

#pragma unroll
    for (int d = 1; d < 32; d <<= 1) {
        float Au = __shfl_up_sync(0xFFFFFFFFu, Ai, d);
        float Hu = __shfl_up_sync(0xFFFFFFFFu, Hi, d);
        if (lane >= d) {
            Hi = fmaf(Ai, Hu, Hi);
            Ai = Au * Ai;
        }
    }
    float Hex = __shfl_up_sync(0xFFFFFFFFu, Hi, 1);
    if (lane == 0) Hex = 0.0f;

    // carry-ins for the 4 local chunks
    float4 Hin;
    Hin.x = Hex;
    Hin.y = fmaf(Av.x, Hex, Hv.x);
    Hin.z = fmaf(A01,  Hex, H01);
    Hin.w = fmaf(A012, Hex, H012);
    *(float4*)(g_Hin + warp * NCHUNK + c0) = Hin;
}

// ---------------------------------------------------------------------------
// Pass 3: recompute with carry-in over 32-step chunks (524288 threads).
// ---------------------------------------------------------------------------
__global__ __launch_bounds__(256) void scan_pass3(float* __restrict__ out) {
    int idx = blockIdx.x * 256 + threadIdx.x;           // 524288
    int ch = idx & (NCH - 1);
    int c  = idx >> 12;                                 // 0..127
    int b = ch >> 10, d = ch & (Dd - 1);
    size_t base = ((size_t)b * Ss + (size_t)c * CLEN) * Dd + d;
    float* orow = out + base;
    float h = g_Hin[ch * NCHUNK + c];
#pragma unroll 8
    for (int t = 0; t < CLEN; t++) {
        float2 p = __half22float2(g_AV[base]);
        base += Dd;
        h = fmaf(p.x, h, p.y);
        *orow = h;
        orow += Dd;
    }
}

// ---------------------------------------------------------------------------
extern "C" void kernel_launch(void* const* d_in, const int* in_sizes, int n_in,
                              void* d_out, int out_size)
{
    const float* x = (const float*)d_in[0];
    const float* W = (const float*)d_in[1];
    float* out = (float*)d_out;

    cudaFuncSetAttribute(gemm_kernel, cudaFuncAttributeMaxDynamicSharedMemorySize, SMEM_DYN);

    const int nsplit = (int)(((size_t)Mm * Kk / 4 + (size_t)Nn * Kk / 4) / 256);
    split_kernel<<<nsplit, 256>>>(x, W);

    gemm_kernel<<<dim3(Nn / TN, Mm / TM), 256, SMEM_DYN>>>();

    scan_pass2<<<(NCH * 32) / 256, 256>>>();
    scan_pass3<<<(NCH * NCHUNK) / 256, 256>>>(out);
}